// round 1
// baseline (speedup 1.0000x reference)
#include <cuda_runtime.h>
#include <cuda_bf16.h>

// Problem constants: B=16, N=256, D=64
#define Bn 16
#define Nn 256
#define Dn 64

__device__ float g_v[Dn];          // v[d] = sum_e a[e]*W[e,d]
__device__ float g_c;              // a·bW + 0.5*ba  (so score = s_i + s_j)
__device__ float g_s[Bn * Nn];     // per-node scalar

// Kernel 0: fold weights. <<<1, 64>>>
__global__ void prep_kernel(const float* __restrict__ W,
                            const float* __restrict__ bW,
                            const float* __restrict__ a,
                            const float* __restrict__ ba) {
    int d = threadIdx.x;
    float acc = 0.f;
#pragma unroll 8
    for (int e = 0; e < Dn; e++) acc += a[e] * W[e * Dn + d];
    g_v[d] = acc;
    if (d == 0) {
        float c = 0.f;
        for (int e = 0; e < Dn; e++) c += a[e] * bW[e];
        g_c = c + 0.5f * ba[0];
    }
}

// Kernel 1: s[b,n] = emb[b,n]·v + c. <<<16, 256>>>
__global__ void s_kernel(const float* __restrict__ emb) {
    int idx = blockIdx.x * Nn + threadIdx.x;
    const float4* e4 = (const float4*)(emb + (size_t)idx * Dn);
    const float4* v4 = (const float4*)g_v;
    float acc = 0.f;
#pragma unroll
    for (int k = 0; k < Dn / 4; k++) {
        float4 e = e4[k];
        float4 v = v4[k];
        acc += e.x * v.x + e.y * v.y + e.z * v.z + e.w * v.w;
    }
    g_s[idx] = acc + g_c;
}

// Kernel 2: one block per (b,i): softmax row -> alphas, outer product row -> value.
// <<<B*N, 256>>>
__global__ __launch_bounds__(256) void main_kernel(
        const float* __restrict__ emb,
        float* __restrict__ out_alpha,   // [B,N,N]
        float* __restrict__ out_value) { // [B,N,N,D]
    const int b = blockIdx.x >> 8;
    const int i = blockIdx.x & 255;
    const int tid = threadIdx.x;

    __shared__ float4 sm_ei[Dn / 4];
    __shared__ float red[8];

    // stage ei = emb[b,i,:] into smem
    if (tid < Dn / 4)
        sm_ei[tid] = ((const float4*)(emb + ((size_t)(b * Nn + i)) * Dn))[tid];

    // score_j = leaky(s_i + s_j)   (ba folded into s)
    const float s_i = g_s[b * Nn + i];
    const float s_j = g_s[b * Nn + tid];
    float x = s_i + s_j;
    x = (x >= 0.f) ? x : 0.01f * x;

    // block max reduce (8 warps)
    float m = x;
#pragma unroll
    for (int o = 16; o; o >>= 1) m = fmaxf(m, __shfl_xor_sync(0xFFFFFFFFu, m, o));
    if ((tid & 31) == 0) red[tid >> 5] = m;
    __syncthreads();                       // also publishes sm_ei
    float bm = red[0];
#pragma unroll
    for (int w = 1; w < 8; w++) bm = fmaxf(bm, red[w]);

    const float e = __expf(x - bm);

    // block sum reduce
    float ss = e;
#pragma unroll
    for (int o = 16; o; o >>= 1) ss += __shfl_xor_sync(0xFFFFFFFFu, ss, o);
    __syncthreads();                       // red reads done before overwrite
    if ((tid & 31) == 0) red[tid >> 5] = ss;
    __syncthreads();
    float tot = 0.f;
#pragma unroll
    for (int w = 0; w < 8; w++) tot += red[w];

    const size_t rowA = (size_t)(b * Nn + i) * Nn;
    out_alpha[rowA + tid] = e / tot;

    // value[b,i,j,:] = ei * ej, streamed as float4.
    // Row = N*D floats = 4096 float4; thread t handles float4 idx = k*256+t.
    // d4 = idx & 15 is the same for every k -> ei float4 is loop-invariant.
    const float4 ei = sm_ei[tid & 15];
    const float4* ej4 = (const float4*)(emb + (size_t)b * Nn * Dn);
    float4* ov = (float4*)out_value + rowA * (Dn / 4);
#pragma unroll
    for (int k = 0; k < 16; k++) {
        int idx = k * 256 + tid;           // 0..4095 ; j = idx>>4, d4 = idx&15
        float4 ej = ej4[idx];              // emb[b] is [N, D] row-major -> direct index
        float4 r;
        r.x = ei.x * ej.x;
        r.y = ei.y * ej.y;
        r.z = ei.z * ej.z;
        r.w = ei.w * ej.w;
        ov[idx] = r;
    }
}

extern "C" void kernel_launch(void* const* d_in, const int* in_sizes, int n_in,
                              void* d_out, int out_size) {
    const float* emb = (const float*)d_in[0];
    const float* W   = (const float*)d_in[1];
    const float* bW  = (const float*)d_in[2];
    const float* a   = (const float*)d_in[3];
    const float* ba  = (const float*)d_in[4];

    float* out_alpha = (float*)d_out;                       // B*N*N floats
    float* out_value = (float*)d_out + (size_t)Bn * Nn * Nn; // B*N*N*D floats

    prep_kernel<<<1, Dn>>>(W, bW, a, ba);
    s_kernel<<<Bn, Nn>>>(emb);
    main_kernel<<<Bn * Nn, 256>>>(emb, out_alpha, out_value);
}